// round 14
// baseline (speedup 1.0000x reference)
#include <cuda_runtime.h>
#include <cuda_fp16.h>
#include <math.h>
#include <stdint.h>

// ---------------------------------------------------------------------------
// dims / output layout
// ---------------------------------------------------------------------------
#define OFF_MAINH 0
#define OFF_MAINC (512*1024)
#define OFF_METAH (2*512*1024)
#define OFF_METAC (2*512*1024 + 512*256)

__device__ float g_metapreA[512*1024];
__device__ float g_metapreB[512*1024];
__device__ float g_z[512*192];
__device__ float g_M1[512*4096];     // gate-interleaved columns: n' = 4j + g
__device__ float g_M2[512*4096];     // gate-interleaved columns
__device__ float g_biasP[4096];      // gate-interleaved bias

// fp16 staging (pre-converted once per launch)
__device__ __align__(16) __half g_xh16[512*2304];    // [input|main_h|meta_h]
__device__ __align__(16) __half g_Wm16[1024*2304];   // [w_ih|w_hh]
__device__ __align__(16) __half g_W116[4096*1024];   // w_iH[task], rows permuted
__device__ __align__(16) __half g_W216[4096*1024];   // w_HH[task], rows permuted

__device__ __forceinline__ uint32_t smem_u32(const void* p) {
    uint32_t a;
    asm("{ .reg .u64 t; cvta.to.shared.u64 t, %1; cvt.u32.u64 %0, t; }"
        : "=r"(a) : "l"(p));
    return a;
}
__device__ __forceinline__ float sigm(float x) { return 1.0f / (1.0f + __expf(-x)); }

__device__ __forceinline__ void ldm4(uint32_t* q, uint32_t addr) {
    asm volatile("ldmatrix.sync.aligned.m8n8.x4.shared.b16 {%0,%1,%2,%3}, [%4];"
        : "=r"(q[0]), "=r"(q[1]), "=r"(q[2]), "=r"(q[3]) : "r"(addr));
}
__device__ __forceinline__ void mma16816(float* d, const uint32_t* a, uint32_t b0, uint32_t b1) {
    asm volatile("mma.sync.aligned.m16n8k16.row.col.f32.f16.f16.f32 "
        "{%0,%1,%2,%3},{%4,%5,%6,%7},{%8,%9},{%0,%1,%2,%3};"
        : "+f"(d[0]), "+f"(d[1]), "+f"(d[2]), "+f"(d[3])
        : "r"(a[0]), "r"(a[1]), "r"(a[2]), "r"(a[3]), "r"(b0), "r"(b1));
}
__device__ __forceinline__ uint32_t pkh(__half a, __half b) {
    __half2 t(a, b);
    return *reinterpret_cast<uint32_t*>(&t);
}
__device__ __forceinline__ uint2 cvt_h(float4 v) {
    return make_uint2(pkh(__float2half_rn(v.x), __float2half_rn(v.y)),
                      pkh(__float2half_rn(v.z), __float2half_rn(v.w)));
}
__device__ __forceinline__ uint4 cvt_h8(float4 a, float4 b) {
    uint2 x = cvt_h(a), y = cvt_h(b);
    return make_uint4(x.x, x.y, y.x, y.y);
}

// ---------------------------------------------------------------------------
// convert pass: fp32 inputs/weights -> fp16 staging (+ permutations)
// ---------------------------------------------------------------------------
#define NU_XH   (512*2304/8)
#define NU_WM   (1024*2304/8)
#define NU_W1   (4096*1024/8)
#define NU_ALL  (NU_XH + NU_WM + 2*NU_W1)
#define NU_B    1024
#define NU_TOT  (NU_ALL + NU_B)

__global__ __launch_bounds__(256) void conv_k(
    const float* __restrict__ input, const float* __restrict__ main_h,
    const float* __restrict__ meta_h,
    const float* __restrict__ w_ih, const float* __restrict__ w_hh,
    const float* __restrict__ w_iH, const float* __restrict__ w_HH,
    const float* __restrict__ bias,
    const int* __restrict__ taskp)
{
    const size_t tstride = (size_t)4096 * 1024;
    const float* w1 = w_iH + (size_t)(*taskp) * tstride;
    const float* w2 = w_HH + (size_t)(*taskp) * tstride;

    for (int u = blockIdx.x * 256 + threadIdx.x; u < NU_TOT; u += gridDim.x * 256) {
        if (u >= NU_ALL) {                 // permuted bias: n' = 4j + g
            int v = u - NU_ALL;
            float4 o = make_float4(bias[v], bias[1024 + v], bias[2048 + v], bias[3072 + v]);
            *reinterpret_cast<float4*>(g_biasP + v * 4) = o;
            continue;
        }
        const float* src;
        uint4* dst;
        if (u < NU_XH) {
            int b = u / 288, c = (u % 288) * 8;
            if (c < 1024)      src = input  + (size_t)b * 1024 + c;
            else if (c < 2048) src = main_h + (size_t)b * 1024 + (c - 1024);
            else               src = meta_h + (size_t)b * 256  + (c - 2048);
            dst = reinterpret_cast<uint4*>(g_xh16) + u;
        } else if (u < NU_XH + NU_WM) {
            int v = u - NU_XH;
            int n = v / 288, c = (v % 288) * 8;
            if (c < 2048) src = w_ih + (size_t)n * 2048 + c;
            else          src = w_hh + (size_t)n * 256 + (c - 2048);
            dst = reinterpret_cast<uint4*>(g_Wm16) + v;
        } else if (u < NU_XH + NU_WM + NU_W1) {
            int v = u - NU_XH - NU_WM;
            int np = v >> 7, c8 = v & 127;               // permuted row np
            int n = (np & 3) * 1024 + (np >> 2);         // source row
            src = w1 + (size_t)n * 1024 + c8 * 8;
            dst = reinterpret_cast<uint4*>(g_W116) + v;
        } else {
            int v = u - NU_XH - NU_WM - NU_W1;
            int np = v >> 7, c8 = v & 127;
            int n = (np & 3) * 1024 + (np >> 2);
            src = w2 + (size_t)n * 1024 + c8 * 8;
            dst = reinterpret_cast<uint4*>(g_W216) + v;
        }
        float4 a = *reinterpret_cast<const float4*>(src);
        float4 b = *reinterpret_cast<const float4*>(src + 4);
        *dst = cvt_h8(a, b);
    }
}

// ---------------------------------------------------------------------------
// biggemm: C[M,N] = A[M,K] @ W[N,K]^T (+bias), pure fp16 mma.sync
// CTA 128x128, BK=32, 256 thr, cp.async 4-stage.  (validated 107us config)
// ---------------------------------------------------------------------------
struct Job16 {
    const __half* A; int lda; int aoff;
    const __half* W; int ldw; int woff;
    const float* bias;
    float* C;
    int N; int nch;
};
struct Jobs4 { Job16 j[4]; };

#define SA 80
#define STG (2*128*SA)
#define BG_SMEM (4*STG)

extern __shared__ char dynsm[];

#define CP16(dst, src) \
    asm volatile("cp.async.ca.shared.global [%0], [%1], 16;" :: "r"(dst), "l"(src))
#define CP_COMMIT() asm volatile("cp.async.commit_group;" ::: "memory")
#define CP_WAIT2()  asm volatile("cp.async.wait_group 2;" ::: "memory")

__global__ __launch_bounds__(256)
void biggemm_k(Jobs4 jobs) {
    const Job16 jb = jobs.j[blockIdx.z];
    const int bn = blockIdx.x * 128;
    if (bn >= jb.N) return;
    const int bm = blockIdx.y * 128;

    const uint32_t sb = smem_u32(dynsm);
    const int tid = threadIdx.x;
    const int lane = tid & 31, wid = tid >> 5;
    const int wm = wid & 3, wn = wid >> 2;
    const uint32_t loff = ((lane & 7) + ((lane >> 3) & 1) * 8) * SA + (lane >> 4) * 16;

    const int r0 = tid >> 2,  s0 = tid & 3;
    const int r1 = (tid + 256) >> 2;
    const __half* agp0 = jb.A + (size_t)(bm + r0) * jb.lda + jb.aoff + s0 * 8;
    const __half* agp1 = jb.A + (size_t)(bm + r1) * jb.lda + jb.aoff + s0 * 8;
    const __half* wgp0 = jb.W + (size_t)(bn + r0) * jb.ldw + jb.woff + s0 * 8;
    const __half* wgp1 = jb.W + (size_t)(bn + r1) * jb.ldw + jb.woff + s0 * 8;
    const uint32_t ao0 = r0 * SA + s0 * 16, ao1 = r1 * SA + s0 * 16;

    auto issue = [&](int c) {
        const uint32_t st = sb + (c & 3) * STG;
        const int k = c * 32;
        CP16(st + ao0,            agp0 + k);
        CP16(st + ao1,            agp1 + k);
        CP16(st + 128 * SA + ao0, wgp0 + k);
        CP16(st + 128 * SA + ao1, wgp1 + k);
    };

    float acc[2][8][4];
#pragma unroll
    for (int i = 0; i < 2; i++)
#pragma unroll
        for (int j = 0; j < 8; j++)
#pragma unroll
            for (int k = 0; k < 4; k++) acc[i][j][k] = 0.0f;

    const int nch = jb.nch;
    issue(0); CP_COMMIT();
    issue(1); CP_COMMIT();
    issue(2); CP_COMMIT();

    for (int c = 0; c < nch; c++) {
        CP_WAIT2();
        __syncthreads();
        if (c + 3 < nch) issue(c + 3);
        CP_COMMIT();

        const uint32_t sA = sb + (c & 3) * STG;
        const uint32_t sW = sA + 128 * SA;
#pragma unroll
        for (int ks = 0; ks < 2; ks++) {
            uint32_t fa[2][4];
#pragma unroll
            for (int mi = 0; mi < 2; mi++)
                ldm4(fa[mi], sA + (wm * 32 + mi * 16) * SA + ks * 32 + loff);
#pragma unroll
            for (int nj = 0; nj < 4; nj++) {
                uint32_t bh[4];
                ldm4(bh, sW + (wn * 64 + nj * 16) * SA + ks * 32 + loff);
#pragma unroll
                for (int mi = 0; mi < 2; mi++) {
                    mma16816(acc[mi][2 * nj],     fa[mi], bh[0], bh[2]);
                    mma16816(acc[mi][2 * nj + 1], fa[mi], bh[1], bh[3]);
                }
            }
        }
    }

    const int g8 = lane >> 2, t2 = (lane & 3) * 2;
#pragma unroll
    for (int mi = 0; mi < 2; mi++) {
        const int rr = bm + wm * 32 + mi * 16 + g8;
#pragma unroll
        for (int j = 0; j < 8; j++) {
            const int cc = bn + wn * 64 + j * 8 + t2;
            float b0 = 0.0f, b1 = 0.0f;
            if (jb.bias) { b0 = jb.bias[cc]; b1 = jb.bias[cc + 1]; }
            float* p0 = jb.C + (size_t)rr * jb.N + cc;
            float* p1 = p0 + (size_t)8 * jb.N;
            p0[0] = acc[mi][j][0] + b0; p0[1] = acc[mi][j][1] + b1;
            p1[0] = acc[mi][j][2] + b0; p1[1] = acc[mi][j][3] + b1;
        }
    }
}

// ---------------------------------------------------------------------------
// zgemm v6: CTA 64x64, gate-interleaved, NO Z staging.
// pre[] kept in registers, per-g fold acc_g*M_g; shuffle-pair epilogue
// (lane^1 exchange) computes LSTM gates and writes main_h/main_c directly.
// smem is read-only after fills -> single __syncthreads total.
// ---------------------------------------------------------------------------
#define SZ 144
#define ZTILE (64*SZ)
#define ZG_SMEM (6*ZTILE)           // A0,A1,A2,W0,W1,W2

__global__ __launch_bounds__(256, 3)
void zgemm_k(const float* __restrict__ wdzi, const float* __restrict__ wdzH,
             const float* __restrict__ wbz,
             const float* __restrict__ main_c, float* __restrict__ out)
{
    const int bn = blockIdx.x * 64;      // permuted column base
    const int bm = blockIdx.y * 64;
    const uint32_t sb = smem_u32(dynsm);
    const uint32_t sWb = sb + 3 * ZTILE;

    const int tid = threadIdx.x;
    const int lane = tid & 31, wid = tid >> 5;
    const int wm = wid & 1, wn = wid >> 1;
    const uint32_t loff = ((lane & 7) + ((lane >> 3) & 1) * 8) * SZ + (lane >> 4) * 16;

    const float* Wsrc[3] = { wdzi, wdzH, wbz };

    // A fill: g_z rows [bm, bm+64) x 192 -> 3 tiles 64x64 fp16
#pragma unroll
    for (int i = 0; i < 12; i++) {
        int u = tid + i * 256;
        int r = u / 48, c4 = u % 48;
        int g = c4 >> 4, cc4 = c4 & 15;
        float4 v = *reinterpret_cast<const float4*>(g_z + (size_t)(bm + r) * 192 + c4 * 4);
        *reinterpret_cast<uint2*>(dynsm + g * ZTILE + r * SZ + cc4 * 8) = cvt_h(v);
    }
    // W fill: 3 x 64 rows x 64 cols, permuted row lookup (n' = 4j+g)
#pragma unroll
    for (int i = 0; i < 12; i++) {
        int u = tid + i * 256;
        int g = u >> 10, r = (u >> 4) & 63, c4 = u & 15;
        int np = bn + r;
        int n = (np & 3) * 1024 + (np >> 2);
        float4 v = *reinterpret_cast<const float4*>(Wsrc[g] + (size_t)n * 64 + c4 * 4);
        *reinterpret_cast<uint2*>(dynsm + 3 * ZTILE + g * ZTILE + r * SZ + c4 * 8) = cvt_h(v);
    }
    __syncthreads();

    const int g8 = lane >> 2, t2 = (lane & 3) * 2;
    // per-lane fragment coordinates
    //   row(mi,h) = bm + wm*32 + mi*16 + h*8 + g8   (batch index)
    //   col(nf)   = bn + wn*16 + nf*8 + t2          (permuted gate column)

    float pre[2][2][4];

#pragma unroll
    for (int g = 0; g < 3; g++) {
        float acc[2][2][4];
#pragma unroll
        for (int i = 0; i < 2; i++)
#pragma unroll
            for (int j = 0; j < 2; j++)
#pragma unroll
                for (int k = 0; k < 4; k++) acc[i][j][k] = 0.0f;

        const uint32_t sA = sb + g * ZTILE;
        const uint32_t sW = sWb + g * ZTILE;
#pragma unroll
        for (int ks = 0; ks < 4; ks++) {
            uint32_t fa[2][4], bh[4];
#pragma unroll
            for (int mi = 0; mi < 2; mi++)
                ldm4(fa[mi], sA + (wm * 32 + mi * 16) * SZ + ks * 32 + loff);
            ldm4(bh, sW + (wn * 16) * SZ + ks * 32 + loff);
#pragma unroll
            for (int mi = 0; mi < 2; mi++) {
                mma16816(acc[mi][0], fa[mi], bh[0], bh[2]);
                mma16816(acc[mi][1], fa[mi], bh[1], bh[3]);
            }
        }

        // fold this GEMM's result into pre[] (registers only)
#pragma unroll
        for (int mi = 0; mi < 2; mi++) {
#pragma unroll
            for (int nf = 0; nf < 2; nf++) {
                const int cp = bn + wn * 16 + nf * 8 + t2;
#pragma unroll
                for (int h = 0; h < 2; h++) {
                    const int b = bm + wm * 32 + mi * 16 + h * 8 + g8;
                    if (g == 0) {
                        float2 m = *reinterpret_cast<const float2*>(g_M1 + (size_t)b * 4096 + cp);
                        pre[mi][nf][2*h]   = acc[mi][nf][2*h]   * m.x;
                        pre[mi][nf][2*h+1] = acc[mi][nf][2*h+1] * m.y;
                    } else if (g == 1) {
                        float2 m = *reinterpret_cast<const float2*>(g_M2 + (size_t)b * 4096 + cp);
                        pre[mi][nf][2*h]   += acc[mi][nf][2*h]   * m.x;
                        pre[mi][nf][2*h+1] += acc[mi][nf][2*h+1] * m.y;
                    } else {
                        float2 bp = *reinterpret_cast<const float2*>(g_biasP + cp);
                        pre[mi][nf][2*h]   += acc[mi][nf][2*h]   + bp.x;
                        pre[mi][nf][2*h+1] += acc[mi][nf][2*h+1] + bp.y;
                    }
                }
            }
        }
    }

    // shuffle-pair epilogue: lanes l (even) / l^1 (odd) jointly own one hidden
    // unit j per (mi,nf,h): even holds gates (i,f), odd holds (g,o).
    const int odd = lane & 1;
    const int jbase = (bn >> 2) + wn * 4 + ((lane & 3) >> 1);
#pragma unroll
    for (int mi = 0; mi < 2; mi++) {
#pragma unroll
        for (int nf = 0; nf < 2; nf++) {
            const int j = jbase + nf * 2;
#pragma unroll
            for (int h = 0; h < 2; h++) {
                float a0 = pre[mi][nf][2*h];
                float a1 = pre[mi][nf][2*h+1];
                float x0 = __shfl_xor_sync(0xffffffffu, a0, 1);
                float x1 = __shfl_xor_sync(0xffffffffu, a1, 1);
                float pi = odd ? x0 : a0;
                float pf = odd ? x1 : a1;
                float pg = odd ? a0 : x0;
                float po = odd ? a1 : x1;
                const int b = bm + wm * 32 + mi * 16 + h * 8 + g8;
                float ci = main_c[(size_t)b * 1024 + j];
                float cn = sigm(pf) * ci + sigm(pi) * tanhf(pg);
                if (!odd) out[OFF_MAINC + (size_t)b * 1024 + j] = cn;
                else      out[OFF_MAINH + (size_t)b * 1024 + j] = sigm(po) * tanhf(cn);
            }
        }
    }
}

// ---------------------------------------------------------------------------
// meta gates + z embeddings fused (sums 2 split-K metapre buffers)
// ---------------------------------------------------------------------------
__global__ __launch_bounds__(256) void metaz_k(
    const float* __restrict__ meta_c, float* __restrict__ out,
    const float* __restrict__ w_hzi, const float* __restrict__ w_hzH,
    const float* __restrict__ w_hzb,
    const float* __restrict__ bias_i, const float* __restrict__ bias_H)
{
    __shared__ float mh[8][256];
    const int b0 = blockIdx.x * 8;
    const int tid = threadIdx.x;
#pragma unroll
    for (int i = 0; i < 8; i++) {
        const int b = b0 + i;
        const float* ra = g_metapreA + (size_t)b * 1024;
        const float* rb = g_metapreB + (size_t)b * 1024;
        float mi = ra[tid] + rb[tid];
        float mf = ra[tid + 256] + rb[tid + 256];
        float mg = ra[tid + 512] + rb[tid + 512];
        float mo = ra[tid + 768] + rb[tid + 768];
        float c = sigm(mf) * meta_c[b * 256 + tid] + sigm(mi) * tanhf(mg);
        float h = sigm(mo) * tanhf(c);
        out[OFF_METAH + b * 256 + tid] = h;
        out[OFF_METAC + b * 256 + tid] = c;
        mh[i][tid] = h;
    }
    __syncthreads();
    if (tid < 192) {
        const float* wrow; float bv;
        if (tid < 64)       { wrow = w_hzi + (size_t)tid * 256;         bv = bias_i[tid]; }
        else if (tid < 128) { wrow = w_hzH + (size_t)(tid - 64) * 256;  bv = bias_H[tid - 64]; }
        else                { wrow = w_hzb + (size_t)(tid - 128) * 256; bv = 0.0f; }
        float acc[8];
#pragma unroll
        for (int r = 0; r < 8; r++) acc[r] = bv;
        for (int k4 = 0; k4 < 64; k4++) {
            float4 w = *reinterpret_cast<const float4*>(wrow + k4 * 4);
#pragma unroll
            for (int r = 0; r < 8; r++) {
                float4 h4 = *reinterpret_cast<const float4*>(&mh[r][k4 * 4]);
                acc[r] += w.x * h4.x + w.y * h4.y + w.z * h4.z + w.w * h4.w;
            }
        }
#pragma unroll
        for (int r = 0; r < 8; r++)
            g_z[(size_t)(b0 + r) * 192 + tid] = acc[r];
    }
}

// ---------------------------------------------------------------------------
// launch
// ---------------------------------------------------------------------------
extern "C" void kernel_launch(void* const* d_in, const int* in_sizes, int n_in,
                              void* d_out, int out_size)
{
    const float* input      = (const float*)d_in[0];
    const float* main_h     = (const float*)d_in[1];
    const float* main_c     = (const float*)d_in[2];
    const float* meta_h     = (const float*)d_in[3];
    const float* meta_c     = (const float*)d_in[4];
    const int*   task       = (const int*)d_in[5];
    const float* w_iH       = (const float*)d_in[6];
    const float* w_HH       = (const float*)d_in[7];
    const float* w_ih       = (const float*)d_in[8];
    const float* w_hh       = (const float*)d_in[9];
    const float* w_hzi      = (const float*)d_in[10];
    const float* w_hzH      = (const float*)d_in[11];
    const float* w_hzb      = (const float*)d_in[12];
    const float* w_dziH     = (const float*)d_in[13];
    const float* w_dzHH     = (const float*)d_in[14];
    const float* w_bzH      = (const float*)d_in[15];
    const float* bias_i     = (const float*)d_in[16];
    const float* bias_H     = (const float*)d_in[17];
    const float* bias       = (const float*)d_in[18];
    const float* bias_hyper = (const float*)d_in[19];
    float* out = (float*)d_out;

    float *p_metapreA, *p_metapreB, *p_M1, *p_M2;
    __half *p_xh16, *p_Wm16, *p_W116, *p_W216;
    cudaGetSymbolAddress((void**)&p_metapreA, g_metapreA);
    cudaGetSymbolAddress((void**)&p_metapreB, g_metapreB);
    cudaGetSymbolAddress((void**)&p_M1, g_M1);
    cudaGetSymbolAddress((void**)&p_M2, g_M2);
    cudaGetSymbolAddress((void**)&p_xh16, g_xh16);
    cudaGetSymbolAddress((void**)&p_Wm16, g_Wm16);
    cudaGetSymbolAddress((void**)&p_W116, g_W116);
    cudaGetSymbolAddress((void**)&p_W216, g_W216);

    cudaFuncSetAttribute(biggemm_k, cudaFuncAttributeMaxDynamicSharedMemorySize, BG_SMEM);
    cudaFuncSetAttribute(zgemm_k,   cudaFuncAttributeMaxDynamicSharedMemorySize, ZG_SMEM);

    conv_k<<<2912, 256>>>(input, main_h, meta_h, w_ih, w_hh, w_iH, w_HH, bias, task);

    Jobs4 J;
    // j0a: metapre K[0,1152)  -> g_metapreA (+bias_hyper)
    J.j[0] = { p_xh16, 2304, 0,    p_Wm16, 2304, 0,    bias_hyper, p_metapreA, 1024, 36 };
    // j0b: metapre K[1152,2304) -> g_metapreB
    J.j[1] = { p_xh16, 2304, 1152, p_Wm16, 2304, 1152, nullptr,    p_metapreB, 1024, 36 };
    // j1: M1 = input @ W_iH[task]^T (permuted cols)
    J.j[2] = { p_xh16, 2304, 0,    p_W116, 1024, 0,    nullptr,    p_M1,       4096, 32 };
    // j2: M2 = main_h @ W_HH[task]^T (permuted cols)
    J.j[3] = { p_xh16, 2304, 1024, p_W216, 1024, 0,    nullptr,    p_M2,       4096, 32 };

    biggemm_k<<<dim3(32, 4, 4), 256, BG_SMEM>>>(J);
    metaz_k<<<64, 256>>>(meta_c, out, w_hzi, w_hzH, w_hzb, bias_i, bias_H);
    zgemm_k<<<dim3(64, 8), 256, ZG_SMEM>>>(w_dziH, w_dzHH, w_bzH, main_c, out);
}

// round 15
// speedup vs baseline: 1.0769x; 1.0769x over previous
#include <cuda_runtime.h>
#include <cuda_fp16.h>
#include <math.h>
#include <stdint.h>

// ---------------------------------------------------------------------------
// dims / output layout
// ---------------------------------------------------------------------------
#define OFF_MAINH 0
#define OFF_MAINC (512*1024)
#define OFF_METAH (2*512*1024)
#define OFF_METAC (2*512*1024 + 512*256)

__device__ float g_metapreA[512*1024];
__device__ float g_metapreB[512*1024];
__device__ float g_z[512*192];
__device__ __align__(16) __half g_M1h[512*4096];   // gate-interleaved cols, fp16
__device__ __align__(16) __half g_M2h[512*4096];   // gate-interleaved cols, fp16
__device__ float g_biasP[4096];                    // gate-interleaved bias

// fp16 staging (pre-converted once per launch)
__device__ __align__(16) __half g_xh16[512*2304];    // [input|main_h|meta_h]
__device__ __align__(16) __half g_Wm16[1024*2304];   // [w_ih|w_hh]
__device__ __align__(16) __half g_W116[4096*1024];   // w_iH[task], rows permuted
__device__ __align__(16) __half g_W216[4096*1024];   // w_HH[task], rows permuted

__device__ __forceinline__ uint32_t smem_u32(const void* p) {
    uint32_t a;
    asm("{ .reg .u64 t; cvta.to.shared.u64 t, %1; cvt.u32.u64 %0, t; }"
        : "=r"(a) : "l"(p));
    return a;
}
__device__ __forceinline__ float sigm(float x) { return 1.0f / (1.0f + __expf(-x)); }

__device__ __forceinline__ void ldm4(uint32_t* q, uint32_t addr) {
    asm volatile("ldmatrix.sync.aligned.m8n8.x4.shared.b16 {%0,%1,%2,%3}, [%4];"
        : "=r"(q[0]), "=r"(q[1]), "=r"(q[2]), "=r"(q[3]) : "r"(addr));
}
__device__ __forceinline__ void mma16816(float* d, const uint32_t* a, uint32_t b0, uint32_t b1) {
    asm volatile("mma.sync.aligned.m16n8k16.row.col.f32.f16.f16.f32 "
        "{%0,%1,%2,%3},{%4,%5,%6,%7},{%8,%9},{%0,%1,%2,%3};"
        : "+f"(d[0]), "+f"(d[1]), "+f"(d[2]), "+f"(d[3])
        : "r"(a[0]), "r"(a[1]), "r"(a[2]), "r"(a[3]), "r"(b0), "r"(b1));
}
__device__ __forceinline__ uint32_t pkh(__half a, __half b) {
    __half2 t(a, b);
    return *reinterpret_cast<uint32_t*>(&t);
}
__device__ __forceinline__ uint2 cvt_h(float4 v) {
    return make_uint2(pkh(__float2half_rn(v.x), __float2half_rn(v.y)),
                      pkh(__float2half_rn(v.z), __float2half_rn(v.w)));
}
__device__ __forceinline__ uint4 cvt_h8(float4 a, float4 b) {
    uint2 x = cvt_h(a), y = cvt_h(b);
    return make_uint4(x.x, x.y, y.x, y.y);
}

// ---------------------------------------------------------------------------
// convert pass: fp32 inputs/weights -> fp16 staging (+ permutations)
// ---------------------------------------------------------------------------
#define NU_XH   (512*2304/8)
#define NU_WM   (1024*2304/8)
#define NU_W1   (4096*1024/8)
#define NU_ALL  (NU_XH + NU_WM + 2*NU_W1)
#define NU_B    1024
#define NU_TOT  (NU_ALL + NU_B)

__global__ __launch_bounds__(256) void conv_k(
    const float* __restrict__ input, const float* __restrict__ main_h,
    const float* __restrict__ meta_h,
    const float* __restrict__ w_ih, const float* __restrict__ w_hh,
    const float* __restrict__ w_iH, const float* __restrict__ w_HH,
    const float* __restrict__ bias,
    const int* __restrict__ taskp)
{
    const size_t tstride = (size_t)4096 * 1024;
    const float* w1 = w_iH + (size_t)(*taskp) * tstride;
    const float* w2 = w_HH + (size_t)(*taskp) * tstride;

    for (int u = blockIdx.x * 256 + threadIdx.x; u < NU_TOT; u += gridDim.x * 256) {
        if (u >= NU_ALL) {                 // permuted bias: n' = 4j + g
            int v = u - NU_ALL;
            float4 o = make_float4(bias[v], bias[1024 + v], bias[2048 + v], bias[3072 + v]);
            *reinterpret_cast<float4*>(g_biasP + v * 4) = o;
            continue;
        }
        const float* src;
        uint4* dst;
        if (u < NU_XH) {
            int b = u / 288, c = (u % 288) * 8;
            if (c < 1024)      src = input  + (size_t)b * 1024 + c;
            else if (c < 2048) src = main_h + (size_t)b * 1024 + (c - 1024);
            else               src = meta_h + (size_t)b * 256  + (c - 2048);
            dst = reinterpret_cast<uint4*>(g_xh16) + u;
        } else if (u < NU_XH + NU_WM) {
            int v = u - NU_XH;
            int n = v / 288, c = (v % 288) * 8;
            if (c < 2048) src = w_ih + (size_t)n * 2048 + c;
            else          src = w_hh + (size_t)n * 256 + (c - 2048);
            dst = reinterpret_cast<uint4*>(g_Wm16) + v;
        } else if (u < NU_XH + NU_WM + NU_W1) {
            int v = u - NU_XH - NU_WM;
            int np = v >> 7, c8 = v & 127;               // permuted row np
            int n = (np & 3) * 1024 + (np >> 2);         // source row
            src = w1 + (size_t)n * 1024 + c8 * 8;
            dst = reinterpret_cast<uint4*>(g_W116) + v;
        } else {
            int v = u - NU_XH - NU_WM - NU_W1;
            int np = v >> 7, c8 = v & 127;
            int n = (np & 3) * 1024 + (np >> 2);
            src = w2 + (size_t)n * 1024 + c8 * 8;
            dst = reinterpret_cast<uint4*>(g_W216) + v;
        }
        float4 a = *reinterpret_cast<const float4*>(src);
        float4 b = *reinterpret_cast<const float4*>(src + 4);
        *dst = cvt_h8(a, b);
    }
}

// ---------------------------------------------------------------------------
// biggemm: C[M,N] = A[M,K] @ W[N,K]^T (+bias), pure fp16 mma.sync
// CTA 128x128, BK=32, 256 thr, cp.async 4-stage.  (validated config)
// half_out=1 -> C is __half* (M1/M2 jobs).
// ---------------------------------------------------------------------------
struct Job16 {
    const __half* A; int lda; int aoff;
    const __half* W; int ldw; int woff;
    const float* bias;
    void* C;
    int N; int nch; int half_out;
};
struct Jobs4 { Job16 j[4]; };

#define SA 80
#define STG (2*128*SA)
#define BG_SMEM (4*STG)

extern __shared__ char dynsm[];

#define CP16(dst, src) \
    asm volatile("cp.async.ca.shared.global [%0], [%1], 16;" :: "r"(dst), "l"(src))
#define CP_COMMIT() asm volatile("cp.async.commit_group;" ::: "memory")
#define CP_WAIT2()  asm volatile("cp.async.wait_group 2;" ::: "memory")

__global__ __launch_bounds__(256)
void biggemm_k(Jobs4 jobs) {
    const Job16 jb = jobs.j[blockIdx.z];
    const int bn = blockIdx.x * 128;
    if (bn >= jb.N) return;
    const int bm = blockIdx.y * 128;

    const uint32_t sb = smem_u32(dynsm);
    const int tid = threadIdx.x;
    const int lane = tid & 31, wid = tid >> 5;
    const int wm = wid & 3, wn = wid >> 2;
    const uint32_t loff = ((lane & 7) + ((lane >> 3) & 1) * 8) * SA + (lane >> 4) * 16;

    const int r0 = tid >> 2,  s0 = tid & 3;
    const int r1 = (tid + 256) >> 2;
    const __half* agp0 = jb.A + (size_t)(bm + r0) * jb.lda + jb.aoff + s0 * 8;
    const __half* agp1 = jb.A + (size_t)(bm + r1) * jb.lda + jb.aoff + s0 * 8;
    const __half* wgp0 = jb.W + (size_t)(bn + r0) * jb.ldw + jb.woff + s0 * 8;
    const __half* wgp1 = jb.W + (size_t)(bn + r1) * jb.ldw + jb.woff + s0 * 8;
    const uint32_t ao0 = r0 * SA + s0 * 16, ao1 = r1 * SA + s0 * 16;

    auto issue = [&](int c) {
        const uint32_t st = sb + (c & 3) * STG;
        const int k = c * 32;
        CP16(st + ao0,            agp0 + k);
        CP16(st + ao1,            agp1 + k);
        CP16(st + 128 * SA + ao0, wgp0 + k);
        CP16(st + 128 * SA + ao1, wgp1 + k);
    };

    float acc[2][8][4];
#pragma unroll
    for (int i = 0; i < 2; i++)
#pragma unroll
        for (int j = 0; j < 8; j++)
#pragma unroll
            for (int k = 0; k < 4; k++) acc[i][j][k] = 0.0f;

    const int nch = jb.nch;
    issue(0); CP_COMMIT();
    issue(1); CP_COMMIT();
    issue(2); CP_COMMIT();

    for (int c = 0; c < nch; c++) {
        CP_WAIT2();
        __syncthreads();
        if (c + 3 < nch) issue(c + 3);
        CP_COMMIT();

        const uint32_t sA = sb + (c & 3) * STG;
        const uint32_t sW = sA + 128 * SA;
#pragma unroll
        for (int ks = 0; ks < 2; ks++) {
            uint32_t fa[2][4];
#pragma unroll
            for (int mi = 0; mi < 2; mi++)
                ldm4(fa[mi], sA + (wm * 32 + mi * 16) * SA + ks * 32 + loff);
#pragma unroll
            for (int nj = 0; nj < 4; nj++) {
                uint32_t bh[4];
                ldm4(bh, sW + (wn * 64 + nj * 16) * SA + ks * 32 + loff);
#pragma unroll
                for (int mi = 0; mi < 2; mi++) {
                    mma16816(acc[mi][2 * nj],     fa[mi], bh[0], bh[2]);
                    mma16816(acc[mi][2 * nj + 1], fa[mi], bh[1], bh[3]);
                }
            }
        }
    }

    const int g8 = lane >> 2, t2 = (lane & 3) * 2;
#pragma unroll
    for (int mi = 0; mi < 2; mi++) {
        const int rr = bm + wm * 32 + mi * 16 + g8;
#pragma unroll
        for (int j = 0; j < 8; j++) {
            const int cc = bn + wn * 64 + j * 8 + t2;
            float b0 = 0.0f, b1 = 0.0f;
            if (jb.bias) { b0 = jb.bias[cc]; b1 = jb.bias[cc + 1]; }
            if (jb.half_out) {
                __half* Ch = (__half*)jb.C;
                __half* p0 = Ch + (size_t)rr * jb.N + cc;
                __half* p1 = p0 + (size_t)8 * jb.N;
                *reinterpret_cast<__half2*>(p0) =
                    __floats2half2_rn(acc[mi][j][0] + b0, acc[mi][j][1] + b1);
                *reinterpret_cast<__half2*>(p1) =
                    __floats2half2_rn(acc[mi][j][2] + b0, acc[mi][j][3] + b1);
            } else {
                float* Cf = (float*)jb.C;
                float* p0 = Cf + (size_t)rr * jb.N + cc;
                float* p1 = p0 + (size_t)8 * jb.N;
                p0[0] = acc[mi][j][0] + b0; p0[1] = acc[mi][j][1] + b1;
                p1[0] = acc[mi][j][2] + b0; p1[1] = acc[mi][j][3] + b1;
            }
        }
    }
}

// ---------------------------------------------------------------------------
// zgemm (R13-validated structure): CTA 64x64, gate-interleaved fused LSTM
// epilogue, per-g smem staging of Z, 3 CTAs/SM.  M1/M2 read as fp16.
// ---------------------------------------------------------------------------
#define SZ 144
#define ZTILE (64*SZ)           // 9216
#define ZPAIR (2*ZTILE)         // 18432: [A_g | W_g], also g's staging region
#define ZG_SMEM (3*ZPAIR)       // 55296
#define ZS 68

__global__ __launch_bounds__(256, 3)
void zgemm_k(const float* __restrict__ wdzi, const float* __restrict__ wdzH,
             const float* __restrict__ wbz,
             const float* __restrict__ main_c, float* __restrict__ out)
{
    const int bn = blockIdx.x * 64;      // permuted column base
    const int bm = blockIdx.y * 64;
    const uint32_t sb = smem_u32(dynsm);

    const int tid = threadIdx.x;
    const int lane = tid & 31, wid = tid >> 5;
    const int wm = wid & 1, wn = wid >> 1;
    const uint32_t loff = ((lane & 7) + ((lane >> 3) & 1) * 8) * SZ + (lane >> 4) * 16;

    const float* Wsrc[3] = { wdzi, wdzH, wbz };

    // A fill: g_z rows [bm, bm+64) x 192 -> tile A_g at pair g
#pragma unroll
    for (int i = 0; i < 12; i++) {
        int u = tid + i * 256;
        int r = u / 48, c4 = u % 48;
        int g = c4 >> 4, cc4 = c4 & 15;
        float4 v = *reinterpret_cast<const float4*>(g_z + (size_t)(bm + r) * 192 + c4 * 4);
        *reinterpret_cast<uint2*>(dynsm + g * ZPAIR + r * SZ + cc4 * 8) = cvt_h(v);
    }
    // W fill: tile W_g at pair g + ZTILE, permuted row lookup (n' = 4j+g)
#pragma unroll
    for (int i = 0; i < 12; i++) {
        int u = tid + i * 256;
        int g = u >> 10, r = (u >> 4) & 63, c4 = u & 15;
        int np = bn + r;
        int n = (np & 3) * 1024 + (np >> 2);
        float4 v = *reinterpret_cast<const float4*>(Wsrc[g] + (size_t)n * 64 + c4 * 4);
        *reinterpret_cast<uint2*>(dynsm + g * ZPAIR + ZTILE + r * SZ + c4 * 8) = cvt_h(v);
    }
    __syncthreads();

    const int g8 = lane >> 2, t2 = (lane & 3) * 2;

    for (int g = 0; g < 3; g++) {
        float acc[2][2][4];
#pragma unroll
        for (int i = 0; i < 2; i++)
#pragma unroll
            for (int j = 0; j < 2; j++)
#pragma unroll
                for (int k = 0; k < 4; k++) acc[i][j][k] = 0.0f;

        const uint32_t sA = sb + g * ZPAIR;
        const uint32_t sW = sA + ZTILE;
#pragma unroll
        for (int ks = 0; ks < 4; ks++) {
            uint32_t fa[2][4], bh[4];
#pragma unroll
            for (int mi = 0; mi < 2; mi++)
                ldm4(fa[mi], sA + (wm * 32 + mi * 16) * SZ + ks * 32 + loff);
            ldm4(bh, sW + (wn * 16) * SZ + ks * 32 + loff);
#pragma unroll
            for (int mi = 0; mi < 2; mi++) {
                mma16816(acc[mi][0], fa[mi], bh[0], bh[2]);
                mma16816(acc[mi][1], fa[mi], bh[1], bh[3]);
            }
        }
        __syncthreads();    // all warps done READING pair g -> safe to overwrite

        float* Zs = reinterpret_cast<float*>(dynsm + g * ZPAIR);
#pragma unroll
        for (int mi = 0; mi < 2; mi++) {
#pragma unroll
            for (int nf = 0; nf < 2; nf++) {
#pragma unroll
                for (int hrow = 0; hrow < 2; hrow++) {
                    int row = wm * 32 + mi * 16 + hrow * 8 + g8;
                    int col = wn * 16 + nf * 8 + t2;
                    float* p = Zs + row * ZS + col;
                    p[0] = acc[mi][nf][2 * hrow];
                    p[1] = acc[mi][nf][2 * hrow + 1];
                }
            }
        }
    }
    __syncthreads();        // staging of g=2 visible to all

    // fused epilogue: thread -> batch row r = tid/4, 4 hidden units
    {
        const int r = tid >> 2, q = tid & 3;
        const int b = bm + r;
        const int colp = bn + q * 16;
        const int J0 = (bn >> 2) + q * 4;
        const size_t moff = (size_t)b * 4096 + colp;
        const float* z1r = reinterpret_cast<const float*>(dynsm)             + r * ZS + q * 16;
        const float* z2r = reinterpret_cast<const float*>(dynsm + ZPAIR)     + r * ZS + q * 16;
        const float* z3r = reinterpret_cast<const float*>(dynsm + 2 * ZPAIR) + r * ZS + q * 16;

        // M1/M2: 16 halves each = 2x uint4 loads
        uint4 m1a = *reinterpret_cast<const uint4*>(g_M1h + moff);
        uint4 m1b = *reinterpret_cast<const uint4*>(g_M1h + moff + 8);
        uint4 m2a = *reinterpret_cast<const uint4*>(g_M2h + moff);
        uint4 m2b = *reinterpret_cast<const uint4*>(g_M2h + moff + 8);
        const __half2* h1a = reinterpret_cast<const __half2*>(&m1a);
        const __half2* h1b = reinterpret_cast<const __half2*>(&m1b);
        const __half2* h2a = reinterpret_cast<const __half2*>(&m2a);
        const __half2* h2b = reinterpret_cast<const __half2*>(&m2b);

        float4 cin = *reinterpret_cast<const float4*>(main_c + (size_t)b * 1024 + J0);
        float4 cv, hv;
#pragma unroll
        for (int f = 0; f < 4; f++) {
            float2 m1lo = __half22float2(f < 2 ? h1a[2*f]   : h1b[2*(f-2)]);
            float2 m1hi = __half22float2(f < 2 ? h1a[2*f+1] : h1b[2*(f-2)+1]);
            float2 m2lo = __half22float2(f < 2 ? h2a[2*f]   : h2b[2*(f-2)]);
            float2 m2hi = __half22float2(f < 2 ? h2a[2*f+1] : h2b[2*(f-2)+1]);
            float4 bp = *reinterpret_cast<const float4*>(g_biasP + colp + f * 4);
            float4 z1 = *reinterpret_cast<const float4*>(z1r + f * 4);
            float4 z2 = *reinterpret_cast<const float4*>(z2r + f * 4);
            float4 z3 = *reinterpret_cast<const float4*>(z3r + f * 4);
            float pi = z1.x * m1lo.x + z2.x * m2lo.x + z3.x + bp.x;
            float pf = z1.y * m1lo.y + z2.y * m2lo.y + z3.y + bp.y;
            float pg = z1.z * m1hi.x + z2.z * m2hi.x + z3.z + bp.z;
            float po = z1.w * m1hi.y + z2.w * m2hi.y + z3.w + bp.w;
            float ci = (&cin.x)[f];
            float cn = sigm(pf) * ci + sigm(pi) * tanhf(pg);
            (&cv.x)[f] = cn;
            (&hv.x)[f] = sigm(po) * tanhf(cn);
        }
        *reinterpret_cast<float4*>(out + OFF_MAINC + (size_t)b * 1024 + J0) = cv;
        *reinterpret_cast<float4*>(out + OFF_MAINH + (size_t)b * 1024 + J0) = hv;
    }
}

// ---------------------------------------------------------------------------
// meta gates + z embeddings fused (sums 2 split-K metapre buffers)
// ---------------------------------------------------------------------------
__global__ __launch_bounds__(256) void metaz_k(
    const float* __restrict__ meta_c, float* __restrict__ out,
    const float* __restrict__ w_hzi, const float* __restrict__ w_hzH,
    const float* __restrict__ w_hzb,
    const float* __restrict__ bias_i, const float* __restrict__ bias_H)
{
    __shared__ float mh[8][256];
    const int b0 = blockIdx.x * 8;
    const int tid = threadIdx.x;
#pragma unroll
    for (int i = 0; i < 8; i++) {
        const int b = b0 + i;
        const float* ra = g_metapreA + (size_t)b * 1024;
        const float* rb = g_metapreB + (size_t)b * 1024;
        float mi = ra[tid] + rb[tid];
        float mf = ra[tid + 256] + rb[tid + 256];
        float mg = ra[tid + 512] + rb[tid + 512];
        float mo = ra[tid + 768] + rb[tid + 768];
        float c = sigm(mf) * meta_c[b * 256 + tid] + sigm(mi) * tanhf(mg);
        float h = sigm(mo) * tanhf(c);
        out[OFF_METAH + b * 256 + tid] = h;
        out[OFF_METAC + b * 256 + tid] = c;
        mh[i][tid] = h;
    }
    __syncthreads();
    if (tid < 192) {
        const float* wrow; float bv;
        if (tid < 64)       { wrow = w_hzi + (size_t)tid * 256;         bv = bias_i[tid]; }
        else if (tid < 128) { wrow = w_hzH + (size_t)(tid - 64) * 256;  bv = bias_H[tid - 64]; }
        else                { wrow = w_hzb + (size_t)(tid - 128) * 256; bv = 0.0f; }
        float acc[8];
#pragma unroll
        for (int r = 0; r < 8; r++) acc[r] = bv;
        for (int k4 = 0; k4 < 64; k4++) {
            float4 w = *reinterpret_cast<const float4*>(wrow + k4 * 4);
#pragma unroll
            for (int r = 0; r < 8; r++) {
                float4 h4 = *reinterpret_cast<const float4*>(&mh[r][k4 * 4]);
                acc[r] += w.x * h4.x + w.y * h4.y + w.z * h4.z + w.w * h4.w;
            }
        }
#pragma unroll
        for (int r = 0; r < 8; r++)
            g_z[(size_t)(b0 + r) * 192 + tid] = acc[r];
    }
}

// ---------------------------------------------------------------------------
// launch
// ---------------------------------------------------------------------------
extern "C" void kernel_launch(void* const* d_in, const int* in_sizes, int n_in,
                              void* d_out, int out_size)
{
    const float* input      = (const float*)d_in[0];
    const float* main_h     = (const float*)d_in[1];
    const float* main_c     = (const float*)d_in[2];
    const float* meta_h     = (const float*)d_in[3];
    const float* meta_c     = (const float*)d_in[4];
    const int*   task       = (const int*)d_in[5];
    const float* w_iH       = (const float*)d_in[6];
    const float* w_HH       = (const float*)d_in[7];
    const float* w_ih       = (const float*)d_in[8];
    const float* w_hh       = (const float*)d_in[9];
    const float* w_hzi      = (const float*)d_in[10];
    const float* w_hzH      = (const float*)d_in[11];
    const float* w_hzb      = (const float*)d_in[12];
    const float* w_dziH     = (const float*)d_in[13];
    const float* w_dzHH     = (const float*)d_in[14];
    const float* w_bzH      = (const float*)d_in[15];
    const float* bias_i     = (const float*)d_in[16];
    const float* bias_H     = (const float*)d_in[17];
    const float* bias       = (const float*)d_in[18];
    const float* bias_hyper = (const float*)d_in[19];
    float* out = (float*)d_out;

    float *p_metapreA, *p_metapreB;
    __half *p_M1h, *p_M2h, *p_xh16, *p_Wm16, *p_W116, *p_W216;
    cudaGetSymbolAddress((void**)&p_metapreA, g_metapreA);
    cudaGetSymbolAddress((void**)&p_metapreB, g_metapreB);
    cudaGetSymbolAddress((void**)&p_M1h, g_M1h);
    cudaGetSymbolAddress((void**)&p_M2h, g_M2h);
    cudaGetSymbolAddress((void**)&p_xh16, g_xh16);
    cudaGetSymbolAddress((void**)&p_Wm16, g_Wm16);
    cudaGetSymbolAddress((void**)&p_W116, g_W116);
    cudaGetSymbolAddress((void**)&p_W216, g_W216);

    cudaFuncSetAttribute(biggemm_k, cudaFuncAttributeMaxDynamicSharedMemorySize, BG_SMEM);
    cudaFuncSetAttribute(zgemm_k,   cudaFuncAttributeMaxDynamicSharedMemorySize, ZG_SMEM);

    conv_k<<<2912, 256>>>(input, main_h, meta_h, w_ih, w_hh, w_iH, w_HH, bias, task);

    Jobs4 J;
    // j0a: metapre K[0,1152)  -> g_metapreA (+bias_hyper), fp32 out
    J.j[0] = { p_xh16, 2304, 0,    p_Wm16, 2304, 0,    bias_hyper, p_metapreA, 1024, 36, 0 };
    // j0b: metapre K[1152,2304) -> g_metapreB, fp32 out
    J.j[1] = { p_xh16, 2304, 1152, p_Wm16, 2304, 1152, nullptr,    p_metapreB, 1024, 36, 0 };
    // j1: M1 = input @ W_iH[task]^T (permuted cols), fp16 out
    J.j[2] = { p_xh16, 2304, 0,    p_W116, 1024, 0,    nullptr,    p_M1h,      4096, 32, 1 };
    // j2: M2 = main_h @ W_HH[task]^T (permuted cols), fp16 out
    J.j[3] = { p_xh16, 2304, 1024, p_W216, 1024, 0,    nullptr,    p_M2h,      4096, 32, 1 };

    biggemm_k<<<dim3(32, 4, 4), 256, BG_SMEM>>>(J);
    metaz_k<<<64, 256>>>(meta_c, out, w_hzi, w_hzH, w_hzb, bias_i, bias_H);
    zgemm_k<<<dim3(64, 8), 256, ZG_SMEM>>>(w_dziH, w_dzHH, w_bzH, main_c, out);
}

// round 16
// speedup vs baseline: 1.0901x; 1.0122x over previous
#include <cuda_runtime.h>
#include <cuda_fp16.h>
#include <math.h>
#include <stdint.h>

// ---------------------------------------------------------------------------
// dims / output layout
// ---------------------------------------------------------------------------
#define OFF_MAINH 0
#define OFF_MAINC (512*1024)
#define OFF_METAH (2*512*1024)
#define OFF_METAC (2*512*1024 + 512*256)

__device__ float g_metapreA[512*1024];
__device__ float g_metapreB[512*1024];
__device__ float g_z[512*192];
__device__ __align__(16) __half g_M1h[512*4096];   // gate-interleaved cols, fp16
__device__ __align__(16) __half g_M2h[512*4096];   // gate-interleaved cols, fp16
__device__ float g_biasP[4096];                    // gate-interleaved bias

// fp16 staging (pre-converted once per launch)
__device__ __align__(16) __half g_xh16[512*2304];    // [input|main_h|meta_h]
__device__ __align__(16) __half g_Wm16[1024*2304];   // [w_ih|w_hh]
__device__ __align__(16) __half g_W116[4096*1024];   // w_iH[task], rows permuted
__device__ __align__(16) __half g_W216[4096*1024];   // w_HH[task], rows permuted

__device__ __forceinline__ uint32_t smem_u32(const void* p) {
    uint32_t a;
    asm("{ .reg .u64 t; cvta.to.shared.u64 t, %1; cvt.u32.u64 %0, t; }"
        : "=r"(a) : "l"(p));
    return a;
}
__device__ __forceinline__ float sigm(float x) { return 1.0f / (1.0f + __expf(-x)); }

__device__ __forceinline__ void ldm4(uint32_t* q, uint32_t addr) {
    asm volatile("ldmatrix.sync.aligned.m8n8.x4.shared.b16 {%0,%1,%2,%3}, [%4];"
        : "=r"(q[0]), "=r"(q[1]), "=r"(q[2]), "=r"(q[3]) : "r"(addr));
}
__device__ __forceinline__ void mma16816(float* d, const uint32_t* a, uint32_t b0, uint32_t b1) {
    asm volatile("mma.sync.aligned.m16n8k16.row.col.f32.f16.f16.f32 "
        "{%0,%1,%2,%3},{%4,%5,%6,%7},{%8,%9},{%0,%1,%2,%3};"
        : "+f"(d[0]), "+f"(d[1]), "+f"(d[2]), "+f"(d[3])
        : "r"(a[0]), "r"(a[1]), "r"(a[2]), "r"(a[3]), "r"(b0), "r"(b1));
}
__device__ __forceinline__ uint32_t pkh(__half a, __half b) {
    __half2 t(a, b);
    return *reinterpret_cast<uint32_t*>(&t);
}
__device__ __forceinline__ uint2 cvt_h(float4 v) {
    return make_uint2(pkh(__float2half_rn(v.x), __float2half_rn(v.y)),
                      pkh(__float2half_rn(v.z), __float2half_rn(v.w)));
}
__device__ __forceinline__ uint4 cvt_h8(float4 a, float4 b) {
    uint2 x = cvt_h(a), y = cvt_h(b);
    return make_uint4(x.x, x.y, y.x, y.y);
}

// ---------------------------------------------------------------------------
// convert pass: fp32 inputs/weights -> fp16 staging (+ permutations)
// ---------------------------------------------------------------------------
#define NU_XH   (512*2304/8)
#define NU_WM   (1024*2304/8)
#define NU_W1   (4096*1024/8)
#define NU_ALL  (NU_XH + NU_WM + 2*NU_W1)
#define NU_B    1024
#define NU_TOT  (NU_ALL + NU_B)

__global__ __launch_bounds__(256) void conv_k(
    const float* __restrict__ input, const float* __restrict__ main_h,
    const float* __restrict__ meta_h,
    const float* __restrict__ w_ih, const float* __restrict__ w_hh,
    const float* __restrict__ w_iH, const float* __restrict__ w_HH,
    const float* __restrict__ bias,
    const int* __restrict__ taskp)
{
    const size_t tstride = (size_t)4096 * 1024;
    const float* w1 = w_iH + (size_t)(*taskp) * tstride;
    const float* w2 = w_HH + (size_t)(*taskp) * tstride;

    for (int u = blockIdx.x * 256 + threadIdx.x; u < NU_TOT; u += gridDim.x * 256) {
        if (u >= NU_ALL) {                 // permuted bias: n' = 4j + g
            int v = u - NU_ALL;
            float4 o = make_float4(bias[v], bias[1024 + v], bias[2048 + v], bias[3072 + v]);
            *reinterpret_cast<float4*>(g_biasP + v * 4) = o;
            continue;
        }
        const float* src;
        uint4* dst;
        if (u < NU_XH) {
            int b = u / 288, c = (u % 288) * 8;
            if (c < 1024)      src = input  + (size_t)b * 1024 + c;
            else if (c < 2048) src = main_h + (size_t)b * 1024 + (c - 1024);
            else               src = meta_h + (size_t)b * 256  + (c - 2048);
            dst = reinterpret_cast<uint4*>(g_xh16) + u;
        } else if (u < NU_XH + NU_WM) {
            int v = u - NU_XH;
            int n = v / 288, c = (v % 288) * 8;
            if (c < 2048) src = w_ih + (size_t)n * 2048 + c;
            else          src = w_hh + (size_t)n * 256 + (c - 2048);
            dst = reinterpret_cast<uint4*>(g_Wm16) + v;
        } else if (u < NU_XH + NU_WM + NU_W1) {
            int v = u - NU_XH - NU_WM;
            int np = v >> 7, c8 = v & 127;               // permuted row np
            int n = (np & 3) * 1024 + (np >> 2);         // source row
            src = w1 + (size_t)n * 1024 + c8 * 8;
            dst = reinterpret_cast<uint4*>(g_W116) + v;
        } else {
            int v = u - NU_XH - NU_WM - NU_W1;
            int np = v >> 7, c8 = v & 127;
            int n = (np & 3) * 1024 + (np >> 2);
            src = w2 + (size_t)n * 1024 + c8 * 8;
            dst = reinterpret_cast<uint4*>(g_W216) + v;
        }
        float4 a = *reinterpret_cast<const float4*>(src);
        float4 b = *reinterpret_cast<const float4*>(src + 4);
        *dst = cvt_h8(a, b);
    }
}

// ---------------------------------------------------------------------------
// biggemm: C[M,N] = A[M,K] @ W[N,K]^T (+bias), pure fp16 mma.sync
// CTA 128x128, BK=32, 256 thr, cp.async 4-stage.  (validated config)
// half_out=1 -> C is __half* (M1/M2 jobs).
// ---------------------------------------------------------------------------
struct Job16 {
    const __half* A; int lda; int aoff;
    const __half* W; int ldw; int woff;
    const float* bias;
    void* C;
    int N; int nch; int half_out;
};
struct Jobs4 { Job16 j[4]; };

#define SA 80
#define STG (2*128*SA)
#define BG_SMEM (4*STG)

extern __shared__ char dynsm[];

#define CP16(dst, src) \
    asm volatile("cp.async.ca.shared.global [%0], [%1], 16;" :: "r"(dst), "l"(src))
#define CP_COMMIT() asm volatile("cp.async.commit_group;" ::: "memory")
#define CP_WAIT2()  asm volatile("cp.async.wait_group 2;" ::: "memory")

__global__ __launch_bounds__(256)
void biggemm_k(Jobs4 jobs) {
    const Job16 jb = jobs.j[blockIdx.z];
    const int bn = blockIdx.x * 128;
    if (bn >= jb.N) return;
    const int bm = blockIdx.y * 128;

    const uint32_t sb = smem_u32(dynsm);
    const int tid = threadIdx.x;
    const int lane = tid & 31, wid = tid >> 5;
    const int wm = wid & 3, wn = wid >> 2;
    const uint32_t loff = ((lane & 7) + ((lane >> 3) & 1) * 8) * SA + (lane >> 4) * 16;

    const int r0 = tid >> 2,  s0 = tid & 3;
    const int r1 = (tid + 256) >> 2;
    const __half* agp0 = jb.A + (size_t)(bm + r0) * jb.lda + jb.aoff + s0 * 8;
    const __half* agp1 = jb.A + (size_t)(bm + r1) * jb.lda + jb.aoff + s0 * 8;
    const __half* wgp0 = jb.W + (size_t)(bn + r0) * jb.ldw + jb.woff + s0 * 8;
    const __half* wgp1 = jb.W + (size_t)(bn + r1) * jb.ldw + jb.woff + s0 * 8;
    const uint32_t ao0 = r0 * SA + s0 * 16, ao1 = r1 * SA + s0 * 16;

    auto issue = [&](int c) {
        const uint32_t st = sb + (c & 3) * STG;
        const int k = c * 32;
        CP16(st + ao0,            agp0 + k);
        CP16(st + ao1,            agp1 + k);
        CP16(st + 128 * SA + ao0, wgp0 + k);
        CP16(st + 128 * SA + ao1, wgp1 + k);
    };

    float acc[2][8][4];
#pragma unroll
    for (int i = 0; i < 2; i++)
#pragma unroll
        for (int j = 0; j < 8; j++)
#pragma unroll
            for (int k = 0; k < 4; k++) acc[i][j][k] = 0.0f;

    const int nch = jb.nch;
    issue(0); CP_COMMIT();
    issue(1); CP_COMMIT();
    issue(2); CP_COMMIT();

    for (int c = 0; c < nch; c++) {
        CP_WAIT2();
        __syncthreads();
        if (c + 3 < nch) issue(c + 3);
        CP_COMMIT();

        const uint32_t sA = sb + (c & 3) * STG;
        const uint32_t sW = sA + 128 * SA;
#pragma unroll
        for (int ks = 0; ks < 2; ks++) {
            uint32_t fa[2][4];
#pragma unroll
            for (int mi = 0; mi < 2; mi++)
                ldm4(fa[mi], sA + (wm * 32 + mi * 16) * SA + ks * 32 + loff);
#pragma unroll
            for (int nj = 0; nj < 4; nj++) {
                uint32_t bh[4];
                ldm4(bh, sW + (wn * 64 + nj * 16) * SA + ks * 32 + loff);
#pragma unroll
                for (int mi = 0; mi < 2; mi++) {
                    mma16816(acc[mi][2 * nj],     fa[mi], bh[0], bh[2]);
                    mma16816(acc[mi][2 * nj + 1], fa[mi], bh[1], bh[3]);
                }
            }
        }
    }

    const int g8 = lane >> 2, t2 = (lane & 3) * 2;
#pragma unroll
    for (int mi = 0; mi < 2; mi++) {
        const int rr = bm + wm * 32 + mi * 16 + g8;
#pragma unroll
        for (int j = 0; j < 8; j++) {
            const int cc = bn + wn * 64 + j * 8 + t2;
            float b0 = 0.0f, b1 = 0.0f;
            if (jb.bias) { b0 = jb.bias[cc]; b1 = jb.bias[cc + 1]; }
            if (jb.half_out) {
                __half* Ch = (__half*)jb.C;
                __half* p0 = Ch + (size_t)rr * jb.N + cc;
                __half* p1 = p0 + (size_t)8 * jb.N;
                *reinterpret_cast<__half2*>(p0) =
                    __floats2half2_rn(acc[mi][j][0] + b0, acc[mi][j][1] + b1);
                *reinterpret_cast<__half2*>(p1) =
                    __floats2half2_rn(acc[mi][j][2] + b0, acc[mi][j][3] + b1);
            } else {
                float* Cf = (float*)jb.C;
                float* p0 = Cf + (size_t)rr * jb.N + cc;
                float* p1 = p0 + (size_t)8 * jb.N;
                p0[0] = acc[mi][j][0] + b0; p0[1] = acc[mi][j][1] + b1;
                p1[0] = acc[mi][j][2] + b0; p1[1] = acc[mi][j][3] + b1;
            }
        }
    }
}

// ---------------------------------------------------------------------------
// zgemm v7: CTA covers 128 batch rows (two 64-row halves) x 64 permuted cols.
// W tiles resident across halves; separate Z staging region; fused LSTM
// epilogue with fp16 M1/M2.  Grid (64,4) = 256 CTAs -> single wave @2 CTA/SM.
// ---------------------------------------------------------------------------
#define SZ 144
#define ZTILE (64*SZ)              // 9216
#define ZA_OFF (3*ZTILE)           // A tiles after W tiles
#define ZSTG_OFF (6*ZTILE)         // 55296
#define ZSTGB 17408                // 64*68*4 per-g staging
#define ZG_SMEM (ZSTG_OFF + 3*ZSTGB)   // 107520
#define ZS 68

__global__ __launch_bounds__(256)
void zgemm_k(const float* __restrict__ wdzi, const float* __restrict__ wdzH,
             const float* __restrict__ wbz,
             const float* __restrict__ main_c, float* __restrict__ out)
{
    const int bn = blockIdx.x * 64;      // permuted column base
    const int bm0 = blockIdx.y * 128;    // 128 batch rows per CTA
    const uint32_t sb = smem_u32(dynsm);

    const int tid = threadIdx.x;
    const int lane = tid & 31, wid = tid >> 5;
    const int wm = wid & 1, wn = wid >> 1;
    const uint32_t loff = ((lane & 7) + ((lane >> 3) & 1) * 8) * SZ + (lane >> 4) * 16;
    const int g8 = lane >> 2, t2 = (lane & 3) * 2;

    const float* Wsrc[3] = { wdzi, wdzH, wbz };

    // W fill (once): tile W_g at g*ZTILE, permuted row lookup (n' = 4j+g)
#pragma unroll
    for (int i = 0; i < 12; i++) {
        int u = tid + i * 256;
        int g = u >> 10, r = (u >> 4) & 63, c4 = u & 15;
        int np = bn + r;
        int n = (np & 3) * 1024 + (np >> 2);
        float4 v = *reinterpret_cast<const float4*>(Wsrc[g] + (size_t)n * 64 + c4 * 4);
        *reinterpret_cast<uint2*>(dynsm + g * ZTILE + r * SZ + c4 * 8) = cvt_h(v);
    }

    for (int h = 0; h < 2; h++) {
        const int bm = bm0 + h * 64;

        // A fill for this half: g_z rows [bm, bm+64) x 192 -> tiles at ZA_OFF
#pragma unroll
        for (int i = 0; i < 12; i++) {
            int u = tid + i * 256;
            int r = u / 48, c4 = u % 48;
            int g = c4 >> 4, cc4 = c4 & 15;
            float4 v = *reinterpret_cast<const float4*>(g_z + (size_t)(bm + r) * 192 + c4 * 4);
            *reinterpret_cast<uint2*>(dynsm + ZA_OFF + g * ZTILE + r * SZ + cc4 * 8) = cvt_h(v);
        }
        __syncthreads();   // A ready; also (h=1) all warps done with epilogue(h=0)

#pragma unroll
        for (int g = 0; g < 3; g++) {
            float acc[2][2][4];
#pragma unroll
            for (int i = 0; i < 2; i++)
#pragma unroll
                for (int j = 0; j < 2; j++)
#pragma unroll
                    for (int k = 0; k < 4; k++) acc[i][j][k] = 0.0f;

            const uint32_t sA = sb + ZA_OFF + g * ZTILE;
            const uint32_t sW = sb + g * ZTILE;
#pragma unroll
            for (int ks = 0; ks < 4; ks++) {
                uint32_t fa[2][4], bh[4];
#pragma unroll
                for (int mi = 0; mi < 2; mi++)
                    ldm4(fa[mi], sA + (wm * 32 + mi * 16) * SZ + ks * 32 + loff);
                ldm4(bh, sW + (wn * 16) * SZ + ks * 32 + loff);
#pragma unroll
                for (int mi = 0; mi < 2; mi++) {
                    mma16816(acc[mi][0], fa[mi], bh[0], bh[2]);
                    mma16816(acc[mi][1], fa[mi], bh[1], bh[3]);
                }
            }

            // stage acc_g into dedicated staging region (disjoint from tiles)
            float* Zs = reinterpret_cast<float*>(dynsm + ZSTG_OFF + g * ZSTGB);
#pragma unroll
            for (int mi = 0; mi < 2; mi++) {
#pragma unroll
                for (int nf = 0; nf < 2; nf++) {
#pragma unroll
                    for (int hrow = 0; hrow < 2; hrow++) {
                        int row = wm * 32 + mi * 16 + hrow * 8 + g8;
                        int col = wn * 16 + nf * 8 + t2;
                        float* p = Zs + row * ZS + col;
                        p[0] = acc[mi][nf][2 * hrow];
                        p[1] = acc[mi][nf][2 * hrow + 1];
                    }
                }
            }
        }
        __syncthreads();   // staging visible

        // fused epilogue: thread -> batch row r = tid/4, 4 hidden units
        {
            const int r = tid >> 2, q = tid & 3;
            const int b = bm + r;
            const int colp = bn + q * 16;
            const int J0 = (bn >> 2) + q * 4;
            const size_t moff = (size_t)b * 4096 + colp;
            const float* z1r = reinterpret_cast<const float*>(dynsm + ZSTG_OFF)             + r * ZS + q * 16;
            const float* z2r = reinterpret_cast<const float*>(dynsm + ZSTG_OFF + ZSTGB)     + r * ZS + q * 16;
            const float* z3r = reinterpret_cast<const float*>(dynsm + ZSTG_OFF + 2 * ZSTGB) + r * ZS + q * 16;

            uint4 m1a = *reinterpret_cast<const uint4*>(g_M1h + moff);
            uint4 m1b = *reinterpret_cast<const uint4*>(g_M1h + moff + 8);
            uint4 m2a = *reinterpret_cast<const uint4*>(g_M2h + moff);
            uint4 m2b = *reinterpret_cast<const uint4*>(g_M2h + moff + 8);
            const __half2* h1a = reinterpret_cast<const __half2*>(&m1a);
            const __half2* h1b = reinterpret_cast<const __half2*>(&m1b);
            const __half2* h2a = reinterpret_cast<const __half2*>(&m2a);
            const __half2* h2b = reinterpret_cast<const __half2*>(&m2b);

            float4 cin = *reinterpret_cast<const float4*>(main_c + (size_t)b * 1024 + J0);
            float4 cv, hv;
#pragma unroll
            for (int f = 0; f < 4; f++) {
                float2 m1lo = __half22float2(f < 2 ? h1a[2*f]   : h1b[2*(f-2)]);
                float2 m1hi = __half22float2(f < 2 ? h1a[2*f+1] : h1b[2*(f-2)+1]);
                float2 m2lo = __half22float2(f < 2 ? h2a[2*f]   : h2b[2*(f-2)]);
                float2 m2hi = __half22float2(f < 2 ? h2a[2*f+1] : h2b[2*(f-2)+1]);
                float4 bp = *reinterpret_cast<const float4*>(g_biasP + colp + f * 4);
                float4 z1 = *reinterpret_cast<const float4*>(z1r + f * 4);
                float4 z2 = *reinterpret_cast<const float4*>(z2r + f * 4);
                float4 z3 = *reinterpret_cast<const float4*>(z3r + f * 4);
                float pi = z1.x * m1lo.x + z2.x * m2lo.x + z3.x + bp.x;
                float pf = z1.y * m1lo.y + z2.y * m2lo.y + z3.y + bp.y;
                float pg = z1.z * m1hi.x + z2.z * m2hi.x + z3.z + bp.z;
                float po = z1.w * m1hi.y + z2.w * m2hi.y + z3.w + bp.w;
                float ci = (&cin.x)[f];
                float cn = sigm(pf) * ci + sigm(pi) * tanhf(pg);
                (&cv.x)[f] = cn;
                (&hv.x)[f] = sigm(po) * tanhf(cn);
            }
            *reinterpret_cast<float4*>(out + OFF_MAINC + (size_t)b * 1024 + J0) = cv;
            *reinterpret_cast<float4*>(out + OFF_MAINH + (size_t)b * 1024 + J0) = hv;
        }
    }
}

// ---------------------------------------------------------------------------
// meta gates + z embeddings fused (sums 2 split-K metapre buffers)
// ---------------------------------------------------------------------------
__global__ __launch_bounds__(256) void metaz_k(
    const float* __restrict__ meta_c, float* __restrict__ out,
    const float* __restrict__ w_hzi, const float* __restrict__ w_hzH,
    const float* __restrict__ w_hzb,
    const float* __restrict__ bias_i, const float* __restrict__ bias_H)
{
    __shared__ float mh[8][256];
    const int b0 = blockIdx.x * 8;
    const int tid = threadIdx.x;
#pragma unroll
    for (int i = 0; i < 8; i++) {
        const int b = b0 + i;
        const float* ra = g_metapreA + (size_t)b * 1024;
        const float* rb = g_metapreB + (size_t)b * 1024;
        float mi = ra[tid] + rb[tid];
        float mf = ra[tid + 256] + rb[tid + 256];
        float mg = ra[tid + 512] + rb[tid + 512];
        float mo = ra[tid + 768] + rb[tid + 768];
        float c = sigm(mf) * meta_c[b * 256 + tid] + sigm(mi) * tanhf(mg);
        float h = sigm(mo) * tanhf(c);
        out[OFF_METAH + b * 256 + tid] = h;
        out[OFF_METAC + b * 256 + tid] = c;
        mh[i][tid] = h;
    }
    __syncthreads();
    if (tid < 192) {
        const float* wrow; float bv;
        if (tid < 64)       { wrow = w_hzi + (size_t)tid * 256;         bv = bias_i[tid]; }
        else if (tid < 128) { wrow = w_hzH + (size_t)(tid - 64) * 256;  bv = bias_H[tid - 64]; }
        else                { wrow = w_hzb + (size_t)(tid - 128) * 256; bv = 0.0f; }
        float acc[8];
#pragma unroll
        for (int r = 0; r < 8; r++) acc[r] = bv;
        for (int k4 = 0; k4 < 64; k4++) {
            float4 w = *reinterpret_cast<const float4*>(wrow + k4 * 4);
#pragma unroll
            for (int r = 0; r < 8; r++) {
                float4 h4 = *reinterpret_cast<const float4*>(&mh[r][k4 * 4]);
                acc[r] += w.x * h4.x + w.y * h4.y + w.z * h4.z + w.w * h4.w;
            }
        }
#pragma unroll
        for (int r = 0; r < 8; r++)
            g_z[(size_t)(b0 + r) * 192 + tid] = acc[r];
    }
}

// ---------------------------------------------------------------------------
// launch
// ---------------------------------------------------------------------------
extern "C" void kernel_launch(void* const* d_in, const int* in_sizes, int n_in,
                              void* d_out, int out_size)
{
    const float* input      = (const float*)d_in[0];
    const float* main_h     = (const float*)d_in[1];
    const float* main_c     = (const float*)d_in[2];
    const float* meta_h     = (const float*)d_in[3];
    const float* meta_c     = (const float*)d_in[4];
    const int*   task       = (const int*)d_in[5];
    const float* w_iH       = (const float*)d_in[6];
    const float* w_HH       = (const float*)d_in[7];
    const float* w_ih       = (const float*)d_in[8];
    const float* w_hh       = (const float*)d_in[9];
    const float* w_hzi      = (const float*)d_in[10];
    const float* w_hzH      = (const float*)d_in[11];
    const float* w_hzb      = (const float*)d_in[12];
    const float* w_dziH     = (const float*)d_in[13];
    const float* w_dzHH     = (const float*)d_in[14];
    const float* w_bzH      = (const float*)d_in[15];
    const float* bias_i     = (const float*)d_in[16];
    const float* bias_H     = (const float*)d_in[17];
    const float* bias       = (const float*)d_in[18];
    const float* bias_hyper = (const float*)d_in[19];
    float* out = (float*)d_out;

    float *p_metapreA, *p_metapreB;
    __half *p_M1h, *p_M2h, *p_xh16, *p_Wm16, *p_W116, *p_W216;
    cudaGetSymbolAddress((void**)&p_metapreA, g_metapreA);
    cudaGetSymbolAddress((void**)&p_metapreB, g_metapreB);
    cudaGetSymbolAddress((void**)&p_M1h, g_M1h);
    cudaGetSymbolAddress((void**)&p_M2h, g_M2h);
    cudaGetSymbolAddress((void**)&p_xh16, g_xh16);
    cudaGetSymbolAddress((void**)&p_Wm16, g_Wm16);
    cudaGetSymbolAddress((void**)&p_W116, g_W116);
    cudaGetSymbolAddress((void**)&p_W216, g_W216);

    cudaFuncSetAttribute(biggemm_k, cudaFuncAttributeMaxDynamicSharedMemorySize, BG_SMEM);
    cudaFuncSetAttribute(zgemm_k,   cudaFuncAttributeMaxDynamicSharedMemorySize, ZG_SMEM);

    conv_k<<<2912, 256>>>(input, main_h, meta_h, w_ih, w_hh, w_iH, w_HH, bias, task);

    Jobs4 J;
    // j0a: metapre K[0,1152)  -> g_metapreA (+bias_hyper), fp32 out
    J.j[0] = { p_xh16, 2304, 0,    p_Wm16, 2304, 0,    bias_hyper, p_metapreA, 1024, 36, 0 };
    // j0b: metapre K[1152,2304) -> g_metapreB, fp32 out
    J.j[1] = { p_xh16, 2304, 1152, p_Wm16, 2304, 1152, nullptr,    p_metapreB, 1024, 36, 0 };
    // j1: M1 = input @ W_iH[task]^T (permuted cols), fp16 out
    J.j[2] = { p_xh16, 2304, 0,    p_W116, 1024, 0,    nullptr,    p_M1h,      4096, 32, 1 };
    // j2: M2 = main_h @ W_HH[task]^T (permuted cols), fp16 out
    J.j[3] = { p_xh16, 2304, 1024, p_W216, 1024, 0,    nullptr,    p_M2h,      4096, 32, 1 };

    biggemm_k<<<dim3(32, 4, 4), 256, BG_SMEM>>>(J);
    metaz_k<<<64, 256>>>(meta_c, out, w_hzi, w_hzH, w_hzb, bias_i, bias_H);
    zgemm_k<<<dim3(64, 4), 256, ZG_SMEM>>>(w_dziH, w_dzHH, w_bzH, main_c, out);
}